// round 6
// baseline (speedup 1.0000x reference)
#include <cuda_runtime.h>
#include <stdint.h>
#include <math.h>

#define NA 180
#define NH 256
#define NW 256
#define ND 256
#define NB 16
#define NT 5
#define NP (NH*NW)
#define NRC (NA*ND)
#define CAP 256
#define NTILE 8
#define TCAP 192
#define MPI 3.14159265358979323846

#define TPC  ((float)(2.0 * MPI))
#define RCPC ((float)(1.0 / (double)((float)(2.0 * MPI))))

// ---------------- device globals (no allocation allowed) ----------------
__device__ float g_C[NA];
__device__ float g_S[NA];
__device__ int   g_row[NA];
__device__ ushort4 g_meta[NA * NH];                         // xlo, xhi, leftbin, rightbin
__device__ __align__(64) float g_img[NP * NB];              // 4 MB, [pixel][batch]
__device__ __align__(64) float g_P[NH * 257 * NB];          // row prefix sums [y][x][b]
__device__ __align__(64) float g_R[NRC * NB];               // residual [a][d][b]
__device__ __align__(64) float g_SN[NRC * NB];              // sino rows transposed [a][d][b]
__device__ __align__(64) float g_corr[NP * NB];             // gather output [y][x][b]
__device__ int g_cnt[NRC];                                  // per-slot run counts
__device__ unsigned g_runs[NRC * CAP];                      // packed runs y|x0<<8|x1<<17
__device__ __align__(16) float4 g_tent[NH * NTILE * TCAP];  // per-(y,tile) angle entries
__device__ int g_tcnt[NH * NTILE];
__device__ unsigned g_maxbits;

// ---------------- angles + counters (launch #1) ----------------
__global__ void k_angles0() {
    int i = threadIdx.x;
    if (i < NA) {
        double ad = (double)i * (MPI / 179.0);
        float ang = (float)ad;
        if (i == NA - 1) ang = (float)MPI;              // linspace endpoint
        g_C[i] = (float)cos((double)ang);
        g_S[i] = (float)sin((double)ang);
        float r = __fmul_rn(__fdiv_rn(ang, (float)MPI), 179.0f);
        g_row[i] = (int)r;                               // trunc, nonneg
    }
    for (int j = i; j < NRC; j += 256) g_cnt[j] = 0;
    if (i == 0) g_maxbits = 0u;
}

// bins + meta + interior run fill + sino transpose + residual seed (launch #2)
__global__ __launch_bounds__(256) void k_binsfill(const float* __restrict__ sino) {
    int a = blockIdx.x, y = threadIdx.x;
    float c = g_C[a], s = g_S[a];
    float tY = __fmul_rn((float)y - 128.0f, s);
    int prev = 0, lb = 0, xlo = 256, lastChange = 0, runStart = 0;
    int cb = a * ND;
    for (int x = 0; x < NW; x++) {
        float xc = (float)x - 128.0f;
        float rot = __fadd_rn(__fmul_rn(xc, c), tY);
        // correctly-rounded rot / 2pi (Markstein, RN + fma)
        float q = __fmul_rn(rot, RCPC);
        float r = __fmaf_rn(-TPC, q, rot);
        q = __fmaf_rn(r, RCPC, q);
        float v = __fmul_rn(q, 256.0f);
        v = truncf(v);
        v = fminf(fmaxf(v, 0.0f), 255.0f);
        int bin = (int)v;
        if (x == 0) { lb = bin; prev = bin; }
        else if (bin != prev) {
            if (prev != 0 && prev != 255) {              // terminal 0/255 -> k_fp2
                int pos = atomicAdd(&g_cnt[cb + prev], 1);
                g_runs[(size_t)(cb + prev) * CAP + pos] =
                    (unsigned)y | ((unsigned)runStart << 8) | ((unsigned)x << 17);
            }
            runStart = x;
            if (xlo == 256) xlo = x;
            lastChange = x;
            prev = bin;
        }
    }
    if (prev != 0 && prev != 255) {
        int pos = atomicAdd(&g_cnt[cb + prev], 1);
        g_runs[(size_t)(cb + prev) * CAP + pos] =
            (unsigned)y | ((unsigned)runStart << 8) | (256u << 17);
    }
    int rb = prev;
    int xhi = lastChange;
    if (xhi < xlo) xhi = xlo;
    g_meta[a * NH + y] = make_ushort4((unsigned short)xlo, (unsigned short)xhi,
                                      (unsigned short)lb, (unsigned short)rb);
    // sino transpose + iteration-0 residual seed (image==0 -> R = sino)
    int row = g_row[a];
    int d = y;
    #pragma unroll
    for (int b = 0; b < NB; b++) {
        float sv = sino[(size_t)b * (NA * ND) + row * ND + d];
        g_SN[(size_t)(cb + d) * NB + b] = sv;
        g_R[(size_t)(cb + d) * NB + b] = sv;
    }
}

// per-(y, 32px-tile) angle entry lists, deterministic ascending-a order (launch #3)
__global__ __launch_bounds__(256) void k_tiles() {
    __shared__ ushort4 mrows[NA * 32];      // meta for 32 consecutive rows
    __shared__ float2 cs[NA];
    int t = threadIdx.x;
    int id = blockIdx.x * 256 + t;          // 2048 ids = 256 y x 8 tiles
    int y0 = (blockIdx.x * 256) >> 3;       // first y of this block (32 rows)
    for (int i = t; i < NA * 32; i += 256) {
        int a = i >> 5, yy = i & 31;
        mrows[i] = g_meta[a * NH + y0 + yy];
    }
    if (t < NA) cs[t] = make_float2(g_C[t], g_S[t]);
    __syncthreads();
    int y = id >> 3, x0 = (id & 7) << 5;
    int yl = y - y0;
    int n = 0;
    float4* dst = g_tent + (size_t)id * TCAP;
    for (int a = 0; a < NA; a++) {
        ushort4 m = mrows[a * 32 + yl];
        int xlo = m.x, xhi = m.y;
        if (xlo < x0 + 32 && xhi > x0) {
            unsigned pk = (unsigned)xlo | ((unsigned)xhi << 9) | ((unsigned)a << 18);
            float2 c = cs[a];
            dst[n++] = make_float4(c.x, c.y, __uint_as_float(pk), 0.0f);
        }
    }
    g_tcnt[id] = n;
}

// interior back-projection gather: warp = 2 px x 16 batch (launch #4 -> ncu)
__global__ __launch_bounds__(512) void k_gather() {
    __shared__ float4 ent[TCAP];
    int blk = blockIdx.x;                   // 2048 = 256 y x 8 tiles
    int y = blk >> 3, x0 = (blk & 7) << 5;
    int t = threadIdx.x;
    int n = g_tcnt[blk];
    for (int i = t; i < n; i += 512) ent[i] = g_tent[(size_t)blk * TCAP + i];
    __syncthreads();
    int w = t >> 5, lane = t & 31;
    int px = x0 + (w << 1) + (lane >> 4);
    int b = lane & 15;
    float xc = (float)px - 128.0f;
    float fy = (float)y - 128.0f;
    float acc = 0.0f;
    for (int i = 0; i < n; i++) {
        float4 E = ent[i];
        unsigned pk = __float_as_uint(E.z);
        int xlo = pk & 511, xhi = (pk >> 9) & 511;
        if (px >= xlo && px < xhi) {
            float tY = __fmul_rn(fy, E.y);
            float rot = __fadd_rn(__fmul_rn(xc, E.x), tY);
            float q = __fmul_rn(rot, RCPC);
            float r = __fmaf_rn(-TPC, q, rot);
            q = __fmaf_rn(r, RCPC, q);
            float v = __fmul_rn(q, 256.0f);
            v = truncf(v);
            v = fminf(fmaxf(v, 0.0f), 255.0f);
            int bin = (int)v;
            int a = (int)(pk >> 18);
            acc += g_R[(size_t)((a << 8) + bin) * NB + b];
        }
    }
    g_corr[(((size_t)y << 8) + px) * NB + b] = acc;
}

// zero image + prefix array (launch #5)
__global__ void k_zero() {
    int i = blockIdx.x * blockDim.x + threadIdx.x;
    int stride = gridDim.x * blockDim.x;
    for (int j = i; j < NP * NB; j += stride) g_img[j] = 0.0f;
    for (int j = i; j < NH * 257 * NB; j += stride) g_P[j] = 0.0f;
}

// scan/update: diff array + scans + image update + fused prefix (+max)
__global__ __launch_bounds__(512) void k_bpu(int last) {
    __shared__ float Dsh[257 * 17];
    __shared__ float blockmax[16];
    int y = blockIdx.x, t = threadIdx.x;
    for (int i = t; i < 257 * 17; i += 512) Dsh[i] = 0.0f;
    __syncthreads();
    // Phase A: saturated/constant step contributions as difference array
    if (t < NA) {
        ushort4 m = g_meta[t * NH + y];
        int xlo = m.x, xhi = m.y, lb = m.z, rb = m.w;
        const float* Ra = g_R + (size_t)t * ND * NB;
        if (xlo > 0) {
            const float* rl = Ra + lb * NB;
            #pragma unroll
            for (int bb = 0; bb < NB; bb++) {
                float v = rl[bb];
                atomicAdd(&Dsh[0 * 17 + bb], v);
                atomicAdd(&Dsh[xlo * 17 + bb], -v);
            }
        }
        if (xhi < 256) {
            const float* rr = Ra + rb * NB;
            #pragma unroll
            for (int bb = 0; bb < NB; bb++)
                atomicAdd(&Dsh[xhi * 17 + bb], rr[bb]);
        }
    }
    __syncthreads();
    int w = t >> 5, lane = t & 31;
    // Phase C: inclusive scan of diff array along x; warp w owns channel w
    {
        float carry = 0.0f;
        for (int seg = 0; seg < 8; seg++) {
            int xx = seg * 32 + lane;
            float v = Dsh[xx * 17 + w];
            #pragma unroll
            for (int off = 1; off < 32; off <<= 1) {
                float nn = __shfl_up_sync(0xffffffffu, v, off);
                if (lane >= off) v += nn;
            }
            v += carry;
            Dsh[xx * 17 + w] = v;
            carry = __shfl_sync(0xffffffffu, v, 31);
        }
    }
    __syncthreads();
    // Phase D: elementwise update over the 4096 row elements (each slot owned)
    const float* crow = g_corr + (size_t)y * NW * NB;
    float* irow = g_img + (size_t)y * NW * NB;
    float mx = -INFINITY;
    #pragma unroll
    for (int k = 0; k < 8; k++) {
        int i = t + k * 512;
        int x = i >> 4, b = i & 15;
        float corr = crow[i] + Dsh[x * 17 + b];
        float nv = irow[i] + __fdiv_rn(corr, 180.0f);
        irow[i] = nv;
        Dsh[x * 17 + b] = nv;                 // stage for prefix (own slot)
        mx = fmaxf(mx, nv);
    }
    if (last) {
        #pragma unroll
        for (int off = 16; off; off >>= 1)
            mx = fmaxf(mx, __shfl_xor_sync(0xffffffffu, mx, off));
        if (lane == 0) blockmax[w] = mx;
    }
    __syncthreads();
    // Phase E: inclusive prefix sums of new row -> g_P; warp w owns channel w
    {
        float carry = 0.0f;
        for (int seg = 0; seg < 8; seg++) {
            int xx = seg * 32 + lane;
            float v = Dsh[xx * 17 + w];
            #pragma unroll
            for (int off = 1; off < 32; off <<= 1) {
                float nn = __shfl_up_sync(0xffffffffu, v, off);
                if (lane >= off) v += nn;
            }
            v += carry;
            Dsh[xx * 17 + w] = v;
            carry = __shfl_sync(0xffffffffu, v, 31);
        }
    }
    __syncthreads();
    // coalesced copy-out (x=0 column of g_P stays 0 from k_zero)
    #pragma unroll
    for (int k = 0; k < 8; k++) {
        int i = t + k * 512;
        int x = i >> 4, b = i & 15;
        g_P[((size_t)y * 257 + x + 1) * NB + b] = Dsh[x * 17 + b];
    }
    if (last && t == 0) {
        float m = blockmax[0];
        #pragma unroll
        for (int k = 1; k < 16; k++) m = fmaxf(m, blockmax[k]);
        unsigned u = __float_as_uint(m);
        u = (u & 0x80000000u) ? ~u : (u | 0x80000000u);
        atomicMax(&g_maxbits, u);
    }
}

// forward projection + residual for interior bins: warp per (a,d), zero atomics
__global__ __launch_bounds__(256) void k_fp() {
    int t = threadIdx.x;
    int wi = blockIdx.x * 8 + (t >> 5);                 // (a,d) index, 46080 total
    int d = wi & 255;
    if (d == 0 || d == 255) return;                      // owned by k_fp2
    int lane = t & 31, half = lane >> 4, b = lane & 15;
    int n = g_cnt[wi];
    const unsigned* runs = g_runs + (size_t)wi * CAP;
    float acc = 0.0f, acc2 = 0.0f;
    int r = half;
    for (; r + 2 < n; r += 4) {
        unsigned r1 = runs[r], r2 = runs[r + 2];
        const float* P1 = g_P + (size_t)(r1 & 255) * 257 * NB;
        const float* P2 = g_P + (size_t)(r2 & 255) * 257 * NB;
        acc  += P1[((r1 >> 17) & 511) * NB + b] - P1[((r1 >> 8) & 511) * NB + b];
        acc2 += P2[((r2 >> 17) & 511) * NB + b] - P2[((r2 >> 8) & 511) * NB + b];
    }
    for (; r < n; r += 2) {
        unsigned rec = runs[r];
        const float* Pr = g_P + (size_t)(rec & 255) * 257 * NB;
        acc += Pr[((rec >> 17) & 511) * NB + b] - Pr[((rec >> 8) & 511) * NB + b];
    }
    acc += acc2;
    acc += __shfl_xor_sync(0xffffffffu, acc, 16);
    if (half == 0)
        g_R[(size_t)wi * NB + b] = g_SN[(size_t)wi * NB + b] - acc;
}

// FP + residual for terminal bins d in {0,255}: block per (a,side)
__global__ __launch_bounds__(256) void k_fp2() {
    __shared__ ushort4 sm2[256];
    __shared__ float red[16 * 17];
    int bx = blockIdx.x;
    int a = bx >> 1;
    int d = (bx & 1) ? 255 : 0;
    int t = threadIdx.x;
    sm2[t] = g_meta[a * NH + t];
    __syncthreads();
    int b = t & 15, yg = t >> 4;
    float acc = 0.0f;
    #pragma unroll 4
    for (int i = 0; i < 16; i++) {
        int y = yg * 16 + i;
        ushort4 m = sm2[y];
        const float* Pr = g_P + (size_t)y * 257 * NB;
        if ((int)m.z == d)        acc += Pr[(int)m.x * NB + b];
        else if ((int)m.w == d)   acc += Pr[256 * NB + b] - Pr[(int)m.y * NB + b];
    }
    red[yg * 17 + b] = acc;
    __syncthreads();
    if (t < 16) {
        float s = 0.0f;
        #pragma unroll
        for (int g = 0; g < 16; g++) s += red[g * 17 + t];
        int wi = a * ND + d;
        g_R[(size_t)wi * NB + t] = g_SN[(size_t)wi * NB + t] - s;
    }
}

// output: clip(image, 0, gmax), coalesced transpose [p][b] -> [b][p]
__global__ __launch_bounds__(256) void k_out(float* __restrict__ out) {
    __shared__ float sh[256 * 17];
    int t = threadIdx.x;
    int p0 = blockIdx.x * 256;
    const float* src = g_img + (size_t)p0 * NB;
    for (int i = t; i < 256 * NB; i += 256) {
        int p = i >> 4, b = i & 15;
        sh[p * 17 + b] = src[i];
    }
    __syncthreads();
    unsigned u = g_maxbits;
    float gm = (u & 0x80000000u) ? __uint_as_float(u ^ 0x80000000u)
                                 : __uint_as_float(~u);
    #pragma unroll
    for (int b = 0; b < NB; b++) {
        float v = sh[t * 17 + b];
        out[(size_t)b * NP + p0 + t] = fminf(fmaxf(v, 0.0f), gm);
    }
}

extern "C" void kernel_launch(void* const* d_in, const int* in_sizes, int n_in,
                              void* d_out, int out_size) {
    const float* sino = (const float*)d_in[0];
    float* out = (float*)d_out;

    k_angles0<<<1, 256>>>();
    k_binsfill<<<NA, 256>>>(sino);       // seeds R = sino (image==0 residual)
    k_tiles<<<8, 256>>>();
    k_gather<<<NH * NTILE, 512>>>();     // launch #4 -> ncu target
    k_zero<<<512, 256>>>();
    k_bpu<<<NH, 512>>>(0);
    for (int it = 1; it < NT; it++) {
        k_fp<<<NRC / 8, 256>>>();
        k_fp2<<<NA * 2, 256>>>();
        k_gather<<<NH * NTILE, 512>>>();
        k_bpu<<<NH, 512>>>(it == NT - 1 ? 1 : 0);
    }
    k_out<<<256, 256>>>(out);
}

// round 7
// speedup vs baseline: 1.1908x; 1.1908x over previous
#include <cuda_runtime.h>
#include <stdint.h>
#include <math.h>

#define NA 180
#define NH 256
#define NW 256
#define ND 256
#define NB 16
#define NT 5
#define NP (NH*NW)
#define NRC (NA*ND)
#define CAP 256
#define CAPP 192
#define MPI 3.14159265358979323846

#define TPC  ((float)(2.0 * MPI))
#define RCPC ((float)(1.0 / (double)((float)(2.0 * MPI))))

// ---------------- device globals (no allocation allowed) ----------------
__device__ float g_C[NA];
__device__ float g_S[NA];
__device__ int   g_row[NA];
__device__ ushort4 g_meta[NA * NH];                         // xlo, xhi, leftbin, rightbin
__device__ __align__(64) float g_img[NP * NB];              // 4 MB, [pixel][batch]
__device__ __align__(64) float g_P[NH * 257 * NB];          // row prefix sums [y][x][b]
__device__ __align__(64) float g_R[NRC * NB];               // residual [a*256+bin][b]
__device__ __align__(64) float g_SN[NRC * NB];              // sino rows transposed
__device__ int g_cnt[NRC];                                  // FP run counts
__device__ unsigned g_runs[NRC * CAP];                      // FP runs y|x0<<8|x1<<17
__device__ int g_pcnt[NP];                                  // per-pixel entry counts
__device__ __align__(8) uint16_t g_plist[NP * CAPP];        // per-pixel entries a<<8|bin
__device__ unsigned g_maxbits;

// launch #1: angles + zero counters
__global__ void k_pre() {
    int gid = blockIdx.x * 256 + threadIdx.x;
    int stride = gridDim.x * 256;
    if (gid < NA) {
        double ad = (double)gid * (MPI / 179.0);
        float ang = (float)ad;
        if (gid == NA - 1) ang = (float)MPI;            // linspace endpoint
        g_C[gid] = (float)cos((double)ang);
        g_S[gid] = (float)sin((double)ang);
        float r = __fmul_rn(__fdiv_rn(ang, (float)MPI), 179.0f);
        g_row[gid] = (int)r;
    }
    for (int j = gid; j < NRC; j += stride) g_cnt[j] = 0;
    for (int j = gid; j < NP; j += stride) g_pcnt[j] = 0;
    if (gid == 0) g_maxbits = 0u;
}

// launch #2: bins + meta + FP run fill + per-pixel BP lists + sino/R seed
__global__ __launch_bounds__(256) void k_binsfill(const float* __restrict__ sino) {
    int a = blockIdx.x, y = threadIdx.x;
    float c = g_C[a], s = g_S[a];
    float tY = __fmul_rn((float)y - 128.0f, s);
    int prev = 0, lb = 0, xlo = 256, lastChange = 0, runStart = 0;
    int cb = a * ND;
    for (int x = 0; x < NW; x++) {
        float xc = (float)x - 128.0f;
        float rot = __fadd_rn(__fmul_rn(xc, c), tY);
        float q = __fmul_rn(rot, RCPC);                  // Markstein /2pi (RN exact)
        float r = __fmaf_rn(-TPC, q, rot);
        q = __fmaf_rn(r, RCPC, q);
        float v = __fmul_rn(q, 256.0f);
        v = truncf(v);
        v = fminf(fmaxf(v, 0.0f), 255.0f);
        int bin = (int)v;
        if (x == 0) { lb = bin; prev = bin; }
        else if (bin != prev) {
            if (prev != 0 && prev != 255) {              // terminal 0/255 -> k_fp2
                int pos = atomicAdd(&g_cnt[cb + prev], 1);
                g_runs[(size_t)(cb + prev) * CAP + pos] =
                    (unsigned)y | ((unsigned)runStart << 8) | ((unsigned)x << 17);
            }
            runStart = x;
            if (xlo == 256) xlo = x;
            lastChange = x;
            prev = bin;
        }
    }
    if (prev != 0 && prev != 255) {
        int pos = atomicAdd(&g_cnt[cb + prev], 1);
        g_runs[(size_t)(cb + prev) * CAP + pos] =
            (unsigned)y | ((unsigned)runStart << 8) | (256u << 17);
    }
    int rb = prev;
    int xhi = lastChange;
    if (xhi < xlo) xhi = xlo;
    g_meta[a * NH + y] = make_ushort4((unsigned short)xlo, (unsigned short)xhi,
                                      (unsigned short)lb, (unsigned short)rb);
    // second pass: per-pixel BP entry lists over interior [xlo, xhi)
    for (int x = xlo; x < xhi; x++) {
        float xc = (float)x - 128.0f;
        float rot = __fadd_rn(__fmul_rn(xc, c), tY);
        float q = __fmul_rn(rot, RCPC);
        float r = __fmaf_rn(-TPC, q, rot);
        q = __fmaf_rn(r, RCPC, q);
        float v = __fmul_rn(q, 256.0f);
        v = truncf(v);
        v = fminf(fmaxf(v, 0.0f), 255.0f);
        int bin = (int)v;
        int p = (y << 8) + x;
        int pos = atomicAdd(&g_pcnt[p], 1);
        g_plist[(size_t)p * CAPP + pos] = (uint16_t)((a << 8) | bin);
    }
    // sino transpose + iteration-0 residual seed (image==0 -> R = sino)
    int row = g_row[a];
    int d = y;
    #pragma unroll
    for (int b = 0; b < NB; b++) {
        float sv = sino[(size_t)b * (NA * ND) + row * ND + d];
        g_SN[(size_t)(cb + d) * NB + b] = sv;
        g_R[(size_t)(cb + d) * NB + b] = sv;
    }
}

// launch #3: zero image + prefix array
__global__ void k_pre2() {
    int i = blockIdx.x * blockDim.x + threadIdx.x;
    int stride = gridDim.x * blockDim.x;
    for (int j = i; j < NP * NB; j += stride) g_img[j] = 0.0f;
    for (int j = i; j < NH * 257 * NB; j += stride) g_P[j] = 0.0f;
}

// launch #4 (profiled): monolithic BP + update + fused prefix (+max)
__global__ __launch_bounds__(512) void k_bp(int last) {
    __shared__ float Dsh[257 * 17];
    __shared__ float Acc[256 * 17];
    __shared__ float Lw[8 * 17];
    __shared__ float blockmax[16];
    int y = blockIdx.x, t = threadIdx.x;
    int w = t >> 5, lane = t & 31;
    for (int i = t; i < 257 * 17; i += 512) Dsh[i] = 0.0f;
    if (t < 8 * 17) Lw[t] = 0.0f;
    __syncthreads();
    // Phase A: terminal-run step contributions as difference array
    if (t < NA) {
        ushort4 m = g_meta[t * NH + y];
        int xlo = m.x, xhi = m.y, lb = m.z, rb = m.w;
        const float* Ra = g_R + (size_t)t * ND * NB;
        if (xlo > 0) {
            const float* rl = Ra + lb * NB;
            #pragma unroll
            for (int bb = 0; bb < NB; bb++) {
                float v = rl[bb];
                atomicAdd(&Lw[w * 17 + bb], v);          // low-contention x=0 partials
                atomicAdd(&Dsh[xlo * 17 + bb], -v);
            }
        }
        if (xhi < 256) {
            const float* rr = Ra + rb * NB;
            #pragma unroll
            for (int bb = 0; bb < NB; bb++)
                atomicAdd(&Dsh[xhi * 17 + bb], rr[bb]);
        }
    }
    // Phase B: interior gather via per-pixel lists; warp = 2 px x 16 batch
    {
        int b = lane & 15;
        int sub = lane >> 4;
        for (int p = 0; p < 8; p++) {
            int px = p * 32 + (w << 1) + sub;
            int pix = (y << 8) + px;
            int n = g_pcnt[pix];
            const uint16_t* lst = g_plist + (size_t)pix * CAPP;
            float acc = 0.0f, acc2 = 0.0f;
            int i = 0;
            for (; i + 1 < n; i += 2) {
                int e0 = lst[i], e1 = lst[i + 1];
                acc  += g_R[(size_t)e0 * NB + b];         // e = a*256+bin = R row
                acc2 += g_R[(size_t)e1 * NB + b];
            }
            if (i < n) acc += g_R[(size_t)lst[i] * NB + b];
            Acc[px * 17 + b] = acc + acc2;
        }
    }
    __syncthreads();
    // combine x=0 partials into Dsh[0]
    if (t < 16) {
        float s = 0.0f;
        #pragma unroll
        for (int k = 0; k < 8; k++) s += Lw[k * 17 + t];
        Dsh[t] += s;
    }
    __syncthreads();
    // Phase C: inclusive scan of diff array along x; warp w owns channel w
    {
        float carry = 0.0f;
        for (int seg = 0; seg < 8; seg++) {
            int xx = seg * 32 + lane;
            float v = Dsh[xx * 17 + w];
            #pragma unroll
            for (int off = 1; off < 32; off <<= 1) {
                float nn = __shfl_up_sync(0xffffffffu, v, off);
                if (lane >= off) v += nn;
            }
            v += carry;
            Dsh[xx * 17 + w] = v;
            carry = __shfl_sync(0xffffffffu, v, 31);
        }
    }
    __syncthreads();
    // Phase D: elementwise update over the 4096 row elements (each slot owned)
    float* irow = g_img + (size_t)y * NW * NB;
    float mx = -INFINITY;
    #pragma unroll
    for (int k = 0; k < 8; k++) {
        int i = t + k * 512;
        int x = i >> 4, b = i & 15;
        float corr = Acc[x * 17 + b] + Dsh[x * 17 + b];
        float nv = irow[i] + __fdiv_rn(corr, 180.0f);
        irow[i] = nv;
        Dsh[x * 17 + b] = nv;                 // stage for prefix (own slot)
        mx = fmaxf(mx, nv);
    }
    if (last) {
        #pragma unroll
        for (int off = 16; off; off >>= 1)
            mx = fmaxf(mx, __shfl_xor_sync(0xffffffffu, mx, off));
        if (lane == 0) blockmax[w] = mx;
    }
    __syncthreads();
    // Phase E: inclusive prefix sums of new row -> g_P; warp w owns channel w
    {
        float carry = 0.0f;
        for (int seg = 0; seg < 8; seg++) {
            int xx = seg * 32 + lane;
            float v = Dsh[xx * 17 + w];
            #pragma unroll
            for (int off = 1; off < 32; off <<= 1) {
                float nn = __shfl_up_sync(0xffffffffu, v, off);
                if (lane >= off) v += nn;
            }
            v += carry;
            Dsh[xx * 17 + w] = v;
            carry = __shfl_sync(0xffffffffu, v, 31);
        }
    }
    __syncthreads();
    #pragma unroll
    for (int k = 0; k < 8; k++) {
        int i = t + k * 512;
        int x = i >> 4, b = i & 15;
        g_P[((size_t)y * 257 + x + 1) * NB + b] = Dsh[x * 17 + b];
    }
    if (last && t == 0) {
        float m = blockmax[0];
        #pragma unroll
        for (int k = 1; k < 16; k++) m = fmaxf(m, blockmax[k]);
        unsigned u = __float_as_uint(m);
        u = (u & 0x80000000u) ? ~u : (u | 0x80000000u);
        atomicMax(&g_maxbits, u);
    }
}

// forward projection + residual for interior bins: warp per (a,d)
__global__ __launch_bounds__(256) void k_fp() {
    int t = threadIdx.x;
    int wi = blockIdx.x * 8 + (t >> 5);
    int d = wi & 255;
    if (d == 0 || d == 255) return;                      // owned by k_fp2
    int lane = t & 31, half = lane >> 4, b = lane & 15;
    int n = g_cnt[wi];
    const unsigned* runs = g_runs + (size_t)wi * CAP;
    float acc = 0.0f, acc2 = 0.0f;
    int r = half;
    for (; r + 2 < n; r += 4) {
        unsigned r1 = runs[r], r2 = runs[r + 2];
        const float* P1 = g_P + (size_t)(r1 & 255) * 257 * NB;
        const float* P2 = g_P + (size_t)(r2 & 255) * 257 * NB;
        acc  += P1[((r1 >> 17) & 511) * NB + b] - P1[((r1 >> 8) & 511) * NB + b];
        acc2 += P2[((r2 >> 17) & 511) * NB + b] - P2[((r2 >> 8) & 511) * NB + b];
    }
    for (; r < n; r += 2) {
        unsigned rec = runs[r];
        const float* Pr = g_P + (size_t)(rec & 255) * 257 * NB;
        acc += Pr[((rec >> 17) & 511) * NB + b] - Pr[((rec >> 8) & 511) * NB + b];
    }
    acc += acc2;
    acc += __shfl_xor_sync(0xffffffffu, acc, 16);
    if (half == 0)
        g_R[(size_t)wi * NB + b] = g_SN[(size_t)wi * NB + b] - acc;
}

// FP + residual for terminal bins d in {0,255}: block per (a,side)
__global__ __launch_bounds__(256) void k_fp2() {
    __shared__ ushort4 sm2[256];
    __shared__ float red[16 * 17];
    int bx = blockIdx.x;
    int a = bx >> 1;
    int d = (bx & 1) ? 255 : 0;
    int t = threadIdx.x;
    sm2[t] = g_meta[a * NH + t];
    __syncthreads();
    int b = t & 15, yg = t >> 4;
    float acc = 0.0f;
    #pragma unroll 4
    for (int i = 0; i < 16; i++) {
        int y = yg * 16 + i;
        ushort4 m = sm2[y];
        const float* Pr = g_P + (size_t)y * 257 * NB;
        if ((int)m.z == d)        acc += Pr[(int)m.x * NB + b];
        else if ((int)m.w == d)   acc += Pr[256 * NB + b] - Pr[(int)m.y * NB + b];
    }
    red[yg * 17 + b] = acc;
    __syncthreads();
    if (t < 16) {
        float s = 0.0f;
        #pragma unroll
        for (int g = 0; g < 16; g++) s += red[g * 17 + t];
        int wi = a * ND + d;
        g_R[(size_t)wi * NB + t] = g_SN[(size_t)wi * NB + t] - s;
    }
}

// output: clip(image, 0, gmax), coalesced transpose [p][b] -> [b][p]
__global__ __launch_bounds__(256) void k_out(float* __restrict__ out) {
    __shared__ float sh[256 * 17];
    int t = threadIdx.x;
    int p0 = blockIdx.x * 256;
    const float* src = g_img + (size_t)p0 * NB;
    for (int i = t; i < 256 * NB; i += 256) {
        int p = i >> 4, b = i & 15;
        sh[p * 17 + b] = src[i];
    }
    __syncthreads();
    unsigned u = g_maxbits;
    float gm = (u & 0x80000000u) ? __uint_as_float(u ^ 0x80000000u)
                                 : __uint_as_float(~u);
    #pragma unroll
    for (int b = 0; b < NB; b++) {
        float v = sh[t * 17 + b];
        out[(size_t)b * NP + p0 + t] = fminf(fmaxf(v, 0.0f), gm);
    }
}

extern "C" void kernel_launch(void* const* d_in, const int* in_sizes, int n_in,
                              void* d_out, int out_size) {
    const float* sino = (const float*)d_in[0];
    float* out = (float*)d_out;

    k_pre<<<64, 256>>>();
    k_binsfill<<<NA, 256>>>(sino);       // seeds R = sino (image==0 residual)
    k_pre2<<<512, 256>>>();
    k_bp<<<NH, 512>>>(0);                // launch #4 -> ncu target
    for (int it = 1; it < NT; it++) {
        k_fp<<<NRC / 8, 256>>>();
        k_fp2<<<NA * 2, 256>>>();
        k_bp<<<NH, 512>>>(it == NT - 1 ? 1 : 0);
    }
    k_out<<<256, 256>>>(out);
}

// round 8
// speedup vs baseline: 2.0387x; 1.7120x over previous
#include <cuda_runtime.h>
#include <stdint.h>
#include <math.h>

#define NA 180
#define NH 256
#define NW 256
#define ND 256
#define NB 16
#define NT 5
#define NP (NH*NW)
#define NRC (NA*ND)
#define CAP 256
#define CAPP 192
#define MPI 3.14159265358979323846

#define TPC  ((float)(2.0 * MPI))
#define RCPC ((float)(1.0 / (double)((float)(2.0 * MPI))))

// ---------------- device globals (no allocation allowed) ----------------
__device__ float g_C[NA];
__device__ float g_S[NA];
__device__ int   g_row[NA];
__device__ ushort4 g_meta[NA * NH];                         // xlo, xhi, leftbin, rightbin
__device__ __align__(64) float g_img[NP * NB];              // 4 MB, [pixel][batch]
__device__ __align__(64) float g_P[NH * 257 * NB];          // row prefix sums [y][x][b]
__device__ __align__(64) float g_R[NRC * NB];               // residual [a*256+bin][b]
__device__ __align__(64) float g_SN[NRC * NB];              // sino rows transposed
__device__ int g_cnt[NRC];                                  // FP run counts
__device__ unsigned g_runs[NRC * CAP];                      // FP runs y|x0<<8|x1<<17
__device__ int g_pcnt[NP];                                  // per-pixel entry counts
__device__ __align__(8) uint16_t g_plist[NP * CAPP];        // per-pixel entries a<<8|bin
__device__ unsigned g_maxbits;

// launch #1: angles + pixel counters
__global__ void k_preA() {
    int gid = blockIdx.x * 256 + threadIdx.x;
    int stride = gridDim.x * 256;
    if (gid < NA) {
        double ad = (double)gid * (MPI / 179.0);
        float ang = (float)ad;
        if (gid == NA - 1) ang = (float)MPI;            // linspace endpoint
        g_C[gid] = (float)cos((double)ang);
        g_S[gid] = (float)sin((double)ang);
        float r = __fmul_rn(__fdiv_rn(ang, (float)MPI), 179.0f);
        g_row[gid] = (int)r;
    }
    for (int j = gid; j < NP; j += stride) g_pcnt[j] = 0;
    if (gid == 0) g_maxbits = 0u;
}

// launch #2: run counters
__global__ void k_preB() {
    int gid = blockIdx.x * 256 + threadIdx.x;
    int stride = gridDim.x * 256;
    for (int j = gid; j < NRC; j += stride) g_cnt[j] = 0;
}

// launch #3: zero image + prefix array
__global__ void k_pre2() {
    int i = blockIdx.x * blockDim.x + threadIdx.x;
    int stride = gridDim.x * blockDim.x;
    for (int j = i; j < NP * NB; j += stride) g_img[j] = 0.0f;
    for (int j = i; j < NH * 257 * NB; j += stride) g_P[j] = 0.0f;
}

// launch #4 (profiled): bins + meta + FP runs + per-pixel BP lists + sino/R seed
__global__ __launch_bounds__(256) void k_binsfill(const float* __restrict__ sino) {
    int a = blockIdx.x, y = threadIdx.x;
    float c = g_C[a], s = g_S[a];
    float tY = __fmul_rn((float)y - 128.0f, s);
    int prev = 0, lb = 0, xlo = 256, lastChange = 0, runStart = 0;
    int cb = a * ND;
    for (int x = 0; x < NW; x++) {
        float xc = (float)x - 128.0f;
        float rot = __fadd_rn(__fmul_rn(xc, c), tY);
        float q = __fmul_rn(rot, RCPC);                  // Markstein /2pi (RN exact)
        float r = __fmaf_rn(-TPC, q, rot);
        q = __fmaf_rn(r, RCPC, q);
        float v = __fmul_rn(q, 256.0f);
        v = truncf(v);
        v = fminf(fmaxf(v, 0.0f), 255.0f);
        int bin = (int)v;
        if (x == 0) { lb = bin; prev = bin; }
        else if (bin != prev) {
            if (prev != 0 && prev != 255) {              // terminal 0/255 -> k_fp2
                int pos = atomicAdd(&g_cnt[cb + prev], 1);
                g_runs[(size_t)(cb + prev) * CAP + pos] =
                    (unsigned)y | ((unsigned)runStart << 8) | ((unsigned)x << 17);
            }
            runStart = x;
            if (xlo == 256) xlo = x;
            lastChange = x;
            prev = bin;
        }
    }
    if (prev != 0 && prev != 255) {
        int pos = atomicAdd(&g_cnt[cb + prev], 1);
        g_runs[(size_t)(cb + prev) * CAP + pos] =
            (unsigned)y | ((unsigned)runStart << 8) | (256u << 17);
    }
    int rb = prev;
    int xhi = lastChange;
    if (xhi < xlo) xhi = xlo;
    g_meta[a * NH + y] = make_ushort4((unsigned short)xlo, (unsigned short)xhi,
                                      (unsigned short)lb, (unsigned short)rb);
    // second pass: per-pixel BP entry lists over interior [xlo, xhi)
    for (int x = xlo; x < xhi; x++) {
        float xc = (float)x - 128.0f;
        float rot = __fadd_rn(__fmul_rn(xc, c), tY);
        float q = __fmul_rn(rot, RCPC);
        float r = __fmaf_rn(-TPC, q, rot);
        q = __fmaf_rn(r, RCPC, q);
        float v = __fmul_rn(q, 256.0f);
        v = truncf(v);
        v = fminf(fmaxf(v, 0.0f), 255.0f);
        int bin = (int)v;
        int p = (y << 8) + x;
        int pos = atomicAdd(&g_pcnt[p], 1);
        g_plist[(size_t)p * CAPP + pos] = (uint16_t)((a << 8) | bin);
    }
    // sino transpose + iteration-0 residual seed (image==0 -> R = sino)
    int row = g_row[a];
    int d = y;
    #pragma unroll
    for (int b = 0; b < NB; b++) {
        float sv = sino[(size_t)b * (NA * ND) + row * ND + d];
        g_SN[(size_t)(cb + d) * NB + b] = sv;
        g_R[(size_t)(cb + d) * NB + b] = sv;
    }
}

// monolithic BP + update + fused prefix (+max)
__global__ __launch_bounds__(512, 1) void k_bp(int last) {
    __shared__ float Dsh[257 * 17];
    __shared__ float Acc[256 * 17];
    __shared__ float Lw[16 * 17];
    __shared__ float blockmax[16];
    int y = blockIdx.x, t = threadIdx.x;
    int w = t >> 5, lane = t & 31;
    for (int i = t; i < 257 * 17; i += 512) Dsh[i] = 0.0f;
    if (t < 16 * 17) Lw[t] = 0.0f;
    __syncthreads();
    // Phase A: terminal-run step contributions, item-parallel over (a,b)
    for (int it = t; it < NA * NB; it += 512) {
        int a = it >> 4, b = it & 15;
        ushort4 m = g_meta[a * NH + y];
        int xlo = m.x, xhi = m.y, lb = m.z, rb = m.w;
        if (xlo > 0) {
            float v = g_R[((size_t)a * ND + lb) * NB + b];
            atomicAdd(&Lw[w * 17 + b], v);               // x=0 partials (hot)
            atomicAdd(&Dsh[xlo * 17 + b], -v);
        }
        if (xhi < 256) {
            float v = g_R[((size_t)a * ND + rb) * NB + b];
            atomicAdd(&Dsh[xhi * 17 + b], v);
        }
    }
    // Phase B: interior gather via per-pixel lists; warp = 2 px x 16 batch, MLP=4
    {
        int b = lane & 15;
        int sub = lane >> 4;
        for (int p = 0; p < 8; p++) {
            int px = p * 32 + (w << 1) + sub;
            int pix = (y << 8) + px;
            int n = g_pcnt[pix];
            const uint16_t* lst = g_plist + (size_t)pix * CAPP;
            float a0 = 0.0f, a1 = 0.0f, a2 = 0.0f, a3 = 0.0f;
            int i = 0;
            for (; i + 3 < n; i += 4) {
                ushort4 e = *(const ushort4*)(lst + i);
                a0 += g_R[(size_t)e.x * NB + b];
                a1 += g_R[(size_t)e.y * NB + b];
                a2 += g_R[(size_t)e.z * NB + b];
                a3 += g_R[(size_t)e.w * NB + b];
            }
            for (; i < n; i++) a0 += g_R[(size_t)lst[i] * NB + b];
            Acc[px * 17 + b] = (a0 + a1) + (a2 + a3);
        }
    }
    __syncthreads();
    // combine x=0 partials into Dsh[0]
    if (t < 16) {
        float s = 0.0f;
        #pragma unroll
        for (int k = 0; k < 16; k++) s += Lw[k * 17 + t];
        Dsh[t] += s;
    }
    __syncthreads();
    // Phase C: inclusive scan along x; warp w owns channel w; lane = 8 elements
    {
        float s[8];
        int base = lane * 8;
        #pragma unroll
        for (int k = 0; k < 8; k++) s[k] = Dsh[(base + k) * 17 + w];
        #pragma unroll
        for (int k = 1; k < 8; k++) s[k] += s[k - 1];
        float tot = s[7], inc = tot;
        #pragma unroll
        for (int off = 1; off < 32; off <<= 1) {
            float nn = __shfl_up_sync(0xffffffffu, inc, off);
            if (lane >= off) inc += nn;
        }
        float excl = inc - tot;
        #pragma unroll
        for (int k = 0; k < 8; k++) Dsh[(base + k) * 17 + w] = s[k] + excl;
    }
    __syncthreads();
    // Phase D: elementwise update over the 4096 row elements (each slot owned)
    float* irow = g_img + (size_t)y * NW * NB;
    float mx = -INFINITY;
    #pragma unroll
    for (int k = 0; k < 8; k++) {
        int i = t + k * 512;
        int x = i >> 4, b = i & 15;
        float corr = Acc[x * 17 + b] + Dsh[x * 17 + b];
        float nv = irow[i] + __fdiv_rn(corr, 180.0f);
        irow[i] = nv;
        Dsh[x * 17 + b] = nv;                 // stage for prefix (own slot)
        mx = fmaxf(mx, nv);
    }
    if (last) {
        #pragma unroll
        for (int off = 16; off; off >>= 1)
            mx = fmaxf(mx, __shfl_xor_sync(0xffffffffu, mx, off));
        if (lane == 0) blockmax[w] = mx;
    }
    __syncthreads();
    // Phase E: inclusive prefix of new row -> g_P; same fast scan
    {
        float s[8];
        int base = lane * 8;
        #pragma unroll
        for (int k = 0; k < 8; k++) s[k] = Dsh[(base + k) * 17 + w];
        #pragma unroll
        for (int k = 1; k < 8; k++) s[k] += s[k - 1];
        float tot = s[7], inc = tot;
        #pragma unroll
        for (int off = 1; off < 32; off <<= 1) {
            float nn = __shfl_up_sync(0xffffffffu, inc, off);
            if (lane >= off) inc += nn;
        }
        float excl = inc - tot;
        #pragma unroll
        for (int k = 0; k < 8; k++) Dsh[(base + k) * 17 + w] = s[k] + excl;
    }
    __syncthreads();
    #pragma unroll
    for (int k = 0; k < 8; k++) {
        int i = t + k * 512;
        int x = i >> 4, b = i & 15;
        g_P[((size_t)y * 257 + x + 1) * NB + b] = Dsh[x * 17 + b];
    }
    if (last && t == 0) {
        float m = blockmax[0];
        #pragma unroll
        for (int k = 1; k < 16; k++) m = fmaxf(m, blockmax[k]);
        unsigned u = __float_as_uint(m);
        u = (u & 0x80000000u) ? ~u : (u | 0x80000000u);
        atomicMax(&g_maxbits, u);
    }
}

// forward projection + residual for interior bins: warp per (a,d)
__global__ __launch_bounds__(256) void k_fp() {
    int t = threadIdx.x;
    int wi = blockIdx.x * 8 + (t >> 5);
    int d = wi & 255;
    if (d == 0 || d == 255) return;                      // owned by k_fp2
    int lane = t & 31, half = lane >> 4, b = lane & 15;
    int n = g_cnt[wi];
    const unsigned* runs = g_runs + (size_t)wi * CAP;
    float acc = 0.0f, acc2 = 0.0f;
    int r = half;
    for (; r + 2 < n; r += 4) {
        unsigned r1 = runs[r], r2 = runs[r + 2];
        const float* P1 = g_P + (size_t)(r1 & 255) * 257 * NB;
        const float* P2 = g_P + (size_t)(r2 & 255) * 257 * NB;
        acc  += P1[((r1 >> 17) & 511) * NB + b] - P1[((r1 >> 8) & 511) * NB + b];
        acc2 += P2[((r2 >> 17) & 511) * NB + b] - P2[((r2 >> 8) & 511) * NB + b];
    }
    for (; r < n; r += 2) {
        unsigned rec = runs[r];
        const float* Pr = g_P + (size_t)(rec & 255) * 257 * NB;
        acc += Pr[((rec >> 17) & 511) * NB + b] - Pr[((rec >> 8) & 511) * NB + b];
    }
    acc += acc2;
    acc += __shfl_xor_sync(0xffffffffu, acc, 16);
    if (half == 0)
        g_R[(size_t)wi * NB + b] = g_SN[(size_t)wi * NB + b] - acc;
}

// FP + residual for terminal bins d in {0,255}: block per (a,side)
__global__ __launch_bounds__(256) void k_fp2() {
    __shared__ ushort4 sm2[256];
    __shared__ float red[16 * 17];
    int bx = blockIdx.x;
    int a = bx >> 1;
    int d = (bx & 1) ? 255 : 0;
    int t = threadIdx.x;
    sm2[t] = g_meta[a * NH + t];
    __syncthreads();
    int b = t & 15, yg = t >> 4;
    float acc = 0.0f;
    #pragma unroll 4
    for (int i = 0; i < 16; i++) {
        int y = yg * 16 + i;
        ushort4 m = sm2[y];
        const float* Pr = g_P + (size_t)y * 257 * NB;
        if ((int)m.z == d)        acc += Pr[(int)m.x * NB + b];
        else if ((int)m.w == d)   acc += Pr[256 * NB + b] - Pr[(int)m.y * NB + b];
    }
    red[yg * 17 + b] = acc;
    __syncthreads();
    if (t < 16) {
        float s = 0.0f;
        #pragma unroll
        for (int g = 0; g < 16; g++) s += red[g * 17 + t];
        int wi = a * ND + d;
        g_R[(size_t)wi * NB + t] = g_SN[(size_t)wi * NB + t] - s;
    }
}

// output: clip(image, 0, gmax), coalesced transpose [p][b] -> [b][p]
__global__ __launch_bounds__(256) void k_out(float* __restrict__ out) {
    __shared__ float sh[256 * 17];
    int t = threadIdx.x;
    int p0 = blockIdx.x * 256;
    const float* src = g_img + (size_t)p0 * NB;
    for (int i = t; i < 256 * NB; i += 256) {
        int p = i >> 4, b = i & 15;
        sh[p * 17 + b] = src[i];
    }
    __syncthreads();
    unsigned u = g_maxbits;
    float gm = (u & 0x80000000u) ? __uint_as_float(u ^ 0x80000000u)
                                 : __uint_as_float(~u);
    #pragma unroll
    for (int b = 0; b < NB; b++) {
        float v = sh[t * 17 + b];
        out[(size_t)b * NP + p0 + t] = fminf(fmaxf(v, 0.0f), gm);
    }
}

extern "C" void kernel_launch(void* const* d_in, const int* in_sizes, int n_in,
                              void* d_out, int out_size) {
    const float* sino = (const float*)d_in[0];
    float* out = (float*)d_out;

    k_preA<<<64, 256>>>();
    k_preB<<<45, 256>>>();
    k_pre2<<<512, 256>>>();
    k_binsfill<<<NA, 256>>>(sino);       // launch #4 -> ncu target
    k_bp<<<NH, 512>>>(0);
    for (int it = 1; it < NT; it++) {
        k_fp<<<NRC / 8, 256>>>();
        k_fp2<<<NA * 2, 256>>>();
        k_bp<<<NH, 512>>>(it == NT - 1 ? 1 : 0);
    }
    k_out<<<256, 256>>>(out);
}

// round 9
// speedup vs baseline: 2.9636x; 1.4537x over previous
#include <cuda_runtime.h>
#include <stdint.h>
#include <math.h>

#define NA 180
#define NH 256
#define NW 256
#define ND 256
#define NB 16
#define NT 5
#define NP (NH*NW)
#define NRC (NA*ND)
#define CAP 256
#define CAPP 192
#define MPI 3.14159265358979323846

#define TPC  ((float)(2.0 * MPI))
#define RCPC ((float)(1.0 / (double)((float)(2.0 * MPI))))

// ---------------- device globals (no allocation allowed) ----------------
__device__ float g_C[NA];
__device__ float g_S[NA];
__device__ int   g_row[NA];
__device__ ushort4 g_meta[NA * NH];                         // xlo, xhi, leftbin, rightbin
__device__ __align__(64) float g_img[NP * NB];              // 4 MB, [pixel][batch]
__device__ __align__(64) float g_P[NH * 257 * NB];          // row prefix sums [y][x][b]
__device__ __align__(64) float g_R[NRC * NB];               // residual [a*256+bin][b]
__device__ __align__(64) float g_SN[NRC * NB];              // sino rows transposed
__device__ int g_cnt[NRC];                                  // FP run counts
__device__ unsigned g_runs[NRC * CAP];                      // FP runs y|x0<<8|x1<<17
__device__ int g_pcnt[NP];                                  // per-pixel entry counts
__device__ __align__(8) uint16_t g_plist[NP * CAPP];        // per-pixel entries a<<8|bin
__device__ unsigned g_maxbits;

// launch #1: angles + zero all counters
__global__ void k_pre() {
    int gid = blockIdx.x * 256 + threadIdx.x;
    int stride = gridDim.x * 256;
    if (gid < NA) {
        double ad = (double)gid * (MPI / 179.0);
        float ang = (float)ad;
        if (gid == NA - 1) ang = (float)MPI;            // linspace endpoint
        g_C[gid] = (float)cos((double)ang);
        g_S[gid] = (float)sin((double)ang);
        float r = __fmul_rn(__fdiv_rn(ang, (float)MPI), 179.0f);
        g_row[gid] = (int)r;
    }
    for (int j = gid; j < NP; j += stride) g_pcnt[j] = 0;
    for (int j = gid; j < NRC; j += stride) g_cnt[j] = 0;
    if (gid == 0) g_maxbits = 0u;
}

// launch #2: zero image + prefix array, sino transpose + iteration-0 R seed
__global__ void k_pre2(const float* __restrict__ sino) {
    int i = blockIdx.x * blockDim.x + threadIdx.x;
    int stride = gridDim.x * blockDim.x;
    for (int j = i; j < NP * NB; j += stride) g_img[j] = 0.0f;
    for (int j = i; j < NH * 257 * NB; j += stride) g_P[j] = 0.0f;
    for (int j = i; j < NRC * NB; j += stride) {
        int b = j & 15;
        int ad = j >> 4;                  // a*256+d
        int a = ad >> 8, d = ad & 255;
        float sv = sino[(size_t)b * (NA * ND) + g_row[a] * ND + d];
        g_SN[j] = sv;
        g_R[j] = sv;                       // image==0 -> residual = sino
    }
}

// launch #3: bins + meta + FP runs + per-pixel BP lists, x-parallel
// grid (180, 8): blockIdx.x = angle, blockIdx.y = 32-row group; 256 threads = x
__global__ __launch_bounds__(256) void k_binsfill() {
    __shared__ int sbin[256];
    __shared__ int s_xlo, s_lastchg;
    int a = blockIdx.x;
    int x = threadIdx.x;
    float c = g_C[a], s = g_S[a];
    float xc = (float)x - 128.0f;
    int cb = a * ND;
    int y0 = blockIdx.y * 32;
    for (int y = y0; y < y0 + 32; y++) {
        float tY = __fmul_rn((float)y - 128.0f, s);
        float rot = __fadd_rn(__fmul_rn(xc, c), tY);
        float q = __fmul_rn(rot, RCPC);                  // Markstein /2pi (RN exact)
        float r = __fmaf_rn(-TPC, q, rot);
        q = __fmaf_rn(r, RCPC, q);
        float v = __fmul_rn(q, 256.0f);
        v = truncf(v);
        v = fminf(fmaxf(v, 0.0f), 255.0f);
        int bin = (int)v;
        sbin[x] = bin;
        if (x == 0) { s_xlo = 256; s_lastchg = 0; }
        __syncthreads();
        bool chg = (x > 0 && bin != sbin[x - 1]);
        if (chg) {
            atomicMin(&s_xlo, x);
            atomicMax(&s_lastchg, x);
        }
        // emit run starting here if bin is interior (not terminal 0/255)
        if ((x == 0 || chg) && bin > 0 && bin < 255) {
            int e = x + 1;
            while (e < 256 && sbin[e] == bin) e++;       // interior runs <= ~4 px
            int pos = atomicAdd(&g_cnt[cb + bin], 1);
            g_runs[(size_t)(cb + bin) * CAP + pos] =
                (unsigned)y | ((unsigned)x << 8) | ((unsigned)e << 17);
        }
        __syncthreads();
        int xlo = s_xlo, xhi = s_lastchg;
        if (xhi < xlo) xhi = xlo;                        // constant row
        if (x >= xlo && x < xhi) {                       // per-pixel BP entry
            int p = (y << 8) + x;
            int pos = atomicAdd(&g_pcnt[p], 1);
            g_plist[(size_t)p * CAPP + pos] = (uint16_t)((a << 8) | bin);
        }
        if (x == 0)
            g_meta[a * NH + y] = make_ushort4((unsigned short)xlo, (unsigned short)xhi,
                                              (unsigned short)sbin[0],
                                              (unsigned short)sbin[255]);
        __syncthreads();                                 // protect sbin for next row
    }
}

// launch #4 (profiled): monolithic BP + update + fused prefix (+max)
__global__ __launch_bounds__(512, 1) void k_bp(int last) {
    __shared__ float Dsh[257 * 17];
    __shared__ float Acc[256 * 17];
    __shared__ float Lw[16 * 17];
    __shared__ float blockmax[16];
    int y = blockIdx.x, t = threadIdx.x;
    int w = t >> 5, lane = t & 31;
    for (int i = t; i < 257 * 17; i += 512) Dsh[i] = 0.0f;
    if (t < 16 * 17) Lw[t] = 0.0f;
    __syncthreads();
    // Phase A: terminal-run step contributions, item-parallel over (a,b)
    for (int it = t; it < NA * NB; it += 512) {
        int a = it >> 4, b = it & 15;
        ushort4 m = g_meta[a * NH + y];
        int xlo = m.x, xhi = m.y, lb = m.z, rb = m.w;
        if (xlo > 0) {
            float v = g_R[((size_t)a * ND + lb) * NB + b];
            atomicAdd(&Lw[w * 17 + b], v);               // x=0 partials (hot)
            atomicAdd(&Dsh[xlo * 17 + b], -v);
        }
        if (xhi < 256) {
            float v = g_R[((size_t)a * ND + rb) * NB + b];
            atomicAdd(&Dsh[xhi * 17 + b], v);
        }
    }
    // Phase B: interior gather via per-pixel lists; warp = 2 px x 16 batch, MLP=4
    {
        int b = lane & 15;
        int sub = lane >> 4;
        for (int p = 0; p < 8; p++) {
            int px = p * 32 + (w << 1) + sub;
            int pix = (y << 8) + px;
            int n = g_pcnt[pix];
            const uint16_t* lst = g_plist + (size_t)pix * CAPP;
            float a0 = 0.0f, a1 = 0.0f, a2 = 0.0f, a3 = 0.0f;
            int i = 0;
            for (; i + 3 < n; i += 4) {
                ushort4 e = *(const ushort4*)(lst + i);
                a0 += g_R[(size_t)e.x * NB + b];
                a1 += g_R[(size_t)e.y * NB + b];
                a2 += g_R[(size_t)e.z * NB + b];
                a3 += g_R[(size_t)e.w * NB + b];
            }
            for (; i < n; i++) a0 += g_R[(size_t)lst[i] * NB + b];
            Acc[px * 17 + b] = (a0 + a1) + (a2 + a3);
        }
    }
    __syncthreads();
    // combine x=0 partials into Dsh[0]
    if (t < 16) {
        float s = 0.0f;
        #pragma unroll
        for (int k = 0; k < 16; k++) s += Lw[k * 17 + t];
        Dsh[t] += s;
    }
    __syncthreads();
    // Phase C: inclusive scan along x; warp w owns channel w; lane = 8 elements
    {
        float s[8];
        int base = lane * 8;
        #pragma unroll
        for (int k = 0; k < 8; k++) s[k] = Dsh[(base + k) * 17 + w];
        #pragma unroll
        for (int k = 1; k < 8; k++) s[k] += s[k - 1];
        float tot = s[7], inc = tot;
        #pragma unroll
        for (int off = 1; off < 32; off <<= 1) {
            float nn = __shfl_up_sync(0xffffffffu, inc, off);
            if (lane >= off) inc += nn;
        }
        float excl = inc - tot;
        #pragma unroll
        for (int k = 0; k < 8; k++) Dsh[(base + k) * 17 + w] = s[k] + excl;
    }
    __syncthreads();
    // Phase D: elementwise update over the 4096 row elements (each slot owned)
    float* irow = g_img + (size_t)y * NW * NB;
    float mx = -INFINITY;
    #pragma unroll
    for (int k = 0; k < 8; k++) {
        int i = t + k * 512;
        int x = i >> 4, b = i & 15;
        float corr = Acc[x * 17 + b] + Dsh[x * 17 + b];
        float nv = irow[i] + __fdiv_rn(corr, 180.0f);
        irow[i] = nv;
        Dsh[x * 17 + b] = nv;                 // stage for prefix (own slot)
        mx = fmaxf(mx, nv);
    }
    if (last) {
        #pragma unroll
        for (int off = 16; off; off >>= 1)
            mx = fmaxf(mx, __shfl_xor_sync(0xffffffffu, mx, off));
        if (lane == 0) blockmax[w] = mx;
    }
    __syncthreads();
    // Phase E: inclusive prefix of new row -> g_P; same fast scan
    {
        float s[8];
        int base = lane * 8;
        #pragma unroll
        for (int k = 0; k < 8; k++) s[k] = Dsh[(base + k) * 17 + w];
        #pragma unroll
        for (int k = 1; k < 8; k++) s[k] += s[k - 1];
        float tot = s[7], inc = tot;
        #pragma unroll
        for (int off = 1; off < 32; off <<= 1) {
            float nn = __shfl_up_sync(0xffffffffu, inc, off);
            if (lane >= off) inc += nn;
        }
        float excl = inc - tot;
        #pragma unroll
        for (int k = 0; k < 8; k++) Dsh[(base + k) * 17 + w] = s[k] + excl;
    }
    __syncthreads();
    #pragma unroll
    for (int k = 0; k < 8; k++) {
        int i = t + k * 512;
        int x = i >> 4, b = i & 15;
        g_P[((size_t)y * 257 + x + 1) * NB + b] = Dsh[x * 17 + b];
    }
    if (last && t == 0) {
        float m = blockmax[0];
        #pragma unroll
        for (int k = 1; k < 16; k++) m = fmaxf(m, blockmax[k]);
        unsigned u = __float_as_uint(m);
        u = (u & 0x80000000u) ? ~u : (u | 0x80000000u);
        atomicMax(&g_maxbits, u);
    }
}

// forward projection + residual for interior bins: warp per (a,d)
__global__ __launch_bounds__(256) void k_fp() {
    int t = threadIdx.x;
    int wi = blockIdx.x * 8 + (t >> 5);
    int d = wi & 255;
    if (d == 0 || d == 255) return;                      // owned by k_fp2
    int lane = t & 31, half = lane >> 4, b = lane & 15;
    int n = g_cnt[wi];
    const unsigned* runs = g_runs + (size_t)wi * CAP;
    float acc = 0.0f, acc2 = 0.0f;
    int r = half;
    for (; r + 2 < n; r += 4) {
        unsigned r1 = runs[r], r2 = runs[r + 2];
        const float* P1 = g_P + (size_t)(r1 & 255) * 257 * NB;
        const float* P2 = g_P + (size_t)(r2 & 255) * 257 * NB;
        acc  += P1[((r1 >> 17) & 511) * NB + b] - P1[((r1 >> 8) & 511) * NB + b];
        acc2 += P2[((r2 >> 17) & 511) * NB + b] - P2[((r2 >> 8) & 511) * NB + b];
    }
    for (; r < n; r += 2) {
        unsigned rec = runs[r];
        const float* Pr = g_P + (size_t)(rec & 255) * 257 * NB;
        acc += Pr[((rec >> 17) & 511) * NB + b] - Pr[((rec >> 8) & 511) * NB + b];
    }
    acc += acc2;
    acc += __shfl_xor_sync(0xffffffffu, acc, 16);
    if (half == 0)
        g_R[(size_t)wi * NB + b] = g_SN[(size_t)wi * NB + b] - acc;
}

// FP + residual for terminal bins d in {0,255}: block per (a,side)
__global__ __launch_bounds__(256) void k_fp2() {
    __shared__ ushort4 sm2[256];
    __shared__ float red[16 * 17];
    int bx = blockIdx.x;
    int a = bx >> 1;
    int d = (bx & 1) ? 255 : 0;
    int t = threadIdx.x;
    sm2[t] = g_meta[a * NH + t];
    __syncthreads();
    int b = t & 15, yg = t >> 4;
    float acc = 0.0f;
    #pragma unroll 4
    for (int i = 0; i < 16; i++) {
        int y = yg * 16 + i;
        ushort4 m = sm2[y];
        const float* Pr = g_P + (size_t)y * 257 * NB;
        if ((int)m.z == d)        acc += Pr[(int)m.x * NB + b];
        else if ((int)m.w == d)   acc += Pr[256 * NB + b] - Pr[(int)m.y * NB + b];
    }
    red[yg * 17 + b] = acc;
    __syncthreads();
    if (t < 16) {
        float s = 0.0f;
        #pragma unroll
        for (int g = 0; g < 16; g++) s += red[g * 17 + t];
        int wi = a * ND + d;
        g_R[(size_t)wi * NB + t] = g_SN[(size_t)wi * NB + t] - s;
    }
}

// output: clip(image, 0, gmax), coalesced transpose [p][b] -> [b][p]
__global__ __launch_bounds__(256) void k_out(float* __restrict__ out) {
    __shared__ float sh[256 * 17];
    int t = threadIdx.x;
    int p0 = blockIdx.x * 256;
    const float* src = g_img + (size_t)p0 * NB;
    for (int i = t; i < 256 * NB; i += 256) {
        int p = i >> 4, b = i & 15;
        sh[p * 17 + b] = src[i];
    }
    __syncthreads();
    unsigned u = g_maxbits;
    float gm = (u & 0x80000000u) ? __uint_as_float(u ^ 0x80000000u)
                                 : __uint_as_float(~u);
    #pragma unroll
    for (int b = 0; b < NB; b++) {
        float v = sh[t * 17 + b];
        out[(size_t)b * NP + p0 + t] = fminf(fmaxf(v, 0.0f), gm);
    }
}

extern "C" void kernel_launch(void* const* d_in, const int* in_sizes, int n_in,
                              void* d_out, int out_size) {
    const float* sino = (const float*)d_in[0];
    float* out = (float*)d_out;

    k_pre<<<64, 256>>>();
    k_pre2<<<512, 256>>>(sino);
    k_binsfill<<<dim3(NA, 8), 256>>>();
    k_bp<<<NH, 512>>>(0);                // launch #4 -> ncu target
    for (int it = 1; it < NT; it++) {
        k_fp<<<NRC / 8, 256>>>();
        k_fp2<<<NA * 2, 256>>>();
        k_bp<<<NH, 512>>>(it == NT - 1 ? 1 : 0);
    }
    k_out<<<256, 256>>>(out);
}

// round 10
// speedup vs baseline: 3.4941x; 1.1790x over previous
#include <cuda_runtime.h>
#include <stdint.h>
#include <math.h>

#define NA 180
#define NH 256
#define NW 256
#define ND 256
#define NB 16
#define NT 5
#define NP (NH*NW)
#define NRC (NA*ND)
#define CAP 256
#define CAPP 192
#define MPI 3.14159265358979323846

#define TPC  ((float)(2.0 * MPI))
#define RCPC ((float)(1.0 / (double)((float)(2.0 * MPI))))

// ---------------- device globals (no allocation allowed) ----------------
__device__ float g_C[NA];
__device__ float g_S[NA];
__device__ int   g_row[NA];
__device__ ushort4 g_meta[NA * NH];                         // xlo, xhi, leftbin, rightbin
__device__ __align__(64) float g_img[NP * NB];              // 4 MB, [pixel][batch]
__device__ __align__(64) float g_P[NH * 257 * NB];          // row prefix sums [y][x][b]
__device__ __align__(64) float g_R[NRC * NB];               // residual [a*256+bin][b]
__device__ __align__(64) float g_SN[NRC * NB];              // sino rows transposed
__device__ int g_cnt[NRC];                                  // FP run counts
__device__ unsigned g_runs[NRC * CAP];                      // FP runs y|x0<<8|x1<<17
__device__ int g_pcnt[NP];                                  // per-pixel entry counts
__device__ __align__(8) uint16_t g_plist[NP * CAPP];        // per-pixel entries a<<8|bin
__device__ unsigned g_maxbits;

// launch #1: angles + zero all counters
__global__ void k_pre() {
    int gid = blockIdx.x * 256 + threadIdx.x;
    int stride = gridDim.x * 256;
    if (gid < NA) {
        double ad = (double)gid * (MPI / 179.0);
        float ang = (float)ad;
        if (gid == NA - 1) ang = (float)MPI;            // linspace endpoint
        g_C[gid] = (float)cos((double)ang);
        g_S[gid] = (float)sin((double)ang);
        float r = __fmul_rn(__fdiv_rn(ang, (float)MPI), 179.0f);
        g_row[gid] = (int)r;
    }
    for (int j = gid; j < NP; j += stride) g_pcnt[j] = 0;
    for (int j = gid; j < NRC; j += stride) g_cnt[j] = 0;
    if (gid == 0) g_maxbits = 0u;
}

// launch #2: zero image + prefix array, sino transpose + iteration-0 R seed
__global__ void k_pre2(const float* __restrict__ sino) {
    int i = blockIdx.x * blockDim.x + threadIdx.x;
    int stride = gridDim.x * blockDim.x;
    for (int j = i; j < NP * NB; j += stride) g_img[j] = 0.0f;
    for (int j = i; j < NH * 257 * NB; j += stride) g_P[j] = 0.0f;
    for (int j = i; j < NRC * NB; j += stride) {
        int b = j & 15;
        int ad = j >> 4;                  // a*256+d
        int a = ad >> 8, d = ad & 255;
        float sv = sino[(size_t)b * (NA * ND) + g_row[a] * ND + d];
        g_SN[j] = sv;
        g_R[j] = sv;                       // image==0 -> residual = sino
    }
}

// launch #3: bins + meta + FP runs + per-pixel BP lists, x-parallel
__global__ __launch_bounds__(256) void k_binsfill() {
    __shared__ int sbin[256];
    __shared__ int s_xlo, s_lastchg;
    int a = blockIdx.x;
    int x = threadIdx.x;
    float c = g_C[a], s = g_S[a];
    float xc = (float)x - 128.0f;
    int cb = a * ND;
    int y0 = blockIdx.y * 32;
    for (int y = y0; y < y0 + 32; y++) {
        float tY = __fmul_rn((float)y - 128.0f, s);
        float rot = __fadd_rn(__fmul_rn(xc, c), tY);
        float q = __fmul_rn(rot, RCPC);                  // Markstein /2pi (RN exact)
        float r = __fmaf_rn(-TPC, q, rot);
        q = __fmaf_rn(r, RCPC, q);
        float v = __fmul_rn(q, 256.0f);
        v = truncf(v);
        v = fminf(fmaxf(v, 0.0f), 255.0f);
        int bin = (int)v;
        sbin[x] = bin;
        if (x == 0) { s_xlo = 256; s_lastchg = 0; }
        __syncthreads();
        bool chg = (x > 0 && bin != sbin[x - 1]);
        if (chg) {
            atomicMin(&s_xlo, x);
            atomicMax(&s_lastchg, x);
        }
        if ((x == 0 || chg) && bin > 0 && bin < 255) {
            int e = x + 1;
            while (e < 256 && sbin[e] == bin) e++;       // interior runs <= ~4 px
            int pos = atomicAdd(&g_cnt[cb + bin], 1);
            g_runs[(size_t)(cb + bin) * CAP + pos] =
                (unsigned)y | ((unsigned)x << 8) | ((unsigned)e << 17);
        }
        __syncthreads();
        int xlo = s_xlo, xhi = s_lastchg;
        if (xhi < xlo) xhi = xlo;                        // constant row
        if (x >= xlo && x < xhi) {                       // per-pixel BP entry
            int p = (y << 8) + x;
            int pos = atomicAdd(&g_pcnt[p], 1);
            g_plist[(size_t)p * CAPP + pos] = (uint16_t)((a << 8) | bin);
        }
        if (x == 0)
            g_meta[a * NH + y] = make_ushort4((unsigned short)xlo, (unsigned short)xhi,
                                              (unsigned short)sbin[0],
                                              (unsigned short)sbin[255]);
        __syncthreads();
    }
}

// monolithic BP + update + fused prefix (+max)
__global__ __launch_bounds__(512, 1) void k_bp(int last) {
    __shared__ float Dsh[257 * 17];
    __shared__ float Acc[256 * 17];
    __shared__ float Lw[16 * 17];
    __shared__ float blockmax[16];
    __shared__ int scnt[256];
    __shared__ ushort4 smeta[NA];
    int y = blockIdx.x, t = threadIdx.x;
    int w = t >> 5, lane = t & 31;
    for (int i = t; i < 257 * 17; i += 512) Dsh[i] = 0.0f;
    if (t < 16 * 17) Lw[t] = 0.0f;
    if (t < 256) scnt[t] = g_pcnt[(y << 8) + t];         // preload counts
    else if (t - 256 < NA) smeta[t - 256] = g_meta[(t - 256) * NH + y];
    __syncthreads();
    // Phase A: terminal-run step contributions, item-parallel over (a,b)
    for (int it = t; it < NA * NB; it += 512) {
        int a = it >> 4, b = it & 15;
        ushort4 m = smeta[a];
        int xlo = m.x, xhi = m.y, lb = m.z, rb = m.w;
        if (xlo > 0) {
            float v = g_R[((size_t)a * ND + lb) * NB + b];
            atomicAdd(&Lw[w * 17 + b], v);               // x=0 partials (hot)
            atomicAdd(&Dsh[xlo * 17 + b], -v);
        }
        if (xhi < 256) {
            float v = g_R[((size_t)a * ND + rb) * NB + b];
            atomicAdd(&Dsh[xhi * 17 + b], v);
        }
    }
    // Phase B: interior gather via per-pixel lists; warp = 2 px x 16 batch, MLP=8
    {
        int b = lane & 15;
        int sub = lane >> 4;
        for (int p = 0; p < 8; p++) {
            int px = p * 32 + (w << 1) + sub;
            int pix = (y << 8) + px;
            int n = scnt[px];
            const uint16_t* lst = g_plist + (size_t)pix * CAPP;
            float a0 = 0.0f, a1 = 0.0f, a2 = 0.0f, a3 = 0.0f;
            float a4 = 0.0f, a5 = 0.0f, a6 = 0.0f, a7 = 0.0f;
            int i = 0;
            for (; i + 7 < n; i += 8) {
                ushort4 e0 = *(const ushort4*)(lst + i);
                ushort4 e1 = *(const ushort4*)(lst + i + 4);
                a0 += g_R[(size_t)e0.x * NB + b];
                a1 += g_R[(size_t)e0.y * NB + b];
                a2 += g_R[(size_t)e0.z * NB + b];
                a3 += g_R[(size_t)e0.w * NB + b];
                a4 += g_R[(size_t)e1.x * NB + b];
                a5 += g_R[(size_t)e1.y * NB + b];
                a6 += g_R[(size_t)e1.z * NB + b];
                a7 += g_R[(size_t)e1.w * NB + b];
            }
            if (i + 3 < n) {
                ushort4 e0 = *(const ushort4*)(lst + i);
                a0 += g_R[(size_t)e0.x * NB + b];
                a1 += g_R[(size_t)e0.y * NB + b];
                a2 += g_R[(size_t)e0.z * NB + b];
                a3 += g_R[(size_t)e0.w * NB + b];
                i += 4;
            }
            for (; i < n; i++) a0 += g_R[(size_t)lst[i] * NB + b];
            Acc[px * 17 + b] = ((a0 + a1) + (a2 + a3)) + ((a4 + a5) + (a6 + a7));
        }
    }
    __syncthreads();
    // combine x=0 partials into Dsh[0]
    if (t < 16) {
        float s = 0.0f;
        #pragma unroll
        for (int k = 0; k < 16; k++) s += Lw[k * 17 + t];
        Dsh[t] += s;
    }
    __syncthreads();
    // Phase C: inclusive scan along x; warp w owns channel w; lane = 8 elements
    {
        float s[8];
        int base = lane * 8;
        #pragma unroll
        for (int k = 0; k < 8; k++) s[k] = Dsh[(base + k) * 17 + w];
        #pragma unroll
        for (int k = 1; k < 8; k++) s[k] += s[k - 1];
        float tot = s[7], inc = tot;
        #pragma unroll
        for (int off = 1; off < 32; off <<= 1) {
            float nn = __shfl_up_sync(0xffffffffu, inc, off);
            if (lane >= off) inc += nn;
        }
        float excl = inc - tot;
        #pragma unroll
        for (int k = 0; k < 8; k++) Dsh[(base + k) * 17 + w] = s[k] + excl;
    }
    __syncthreads();
    // Phase D: elementwise update over the 4096 row elements (each slot owned)
    float* irow = g_img + (size_t)y * NW * NB;
    float mx = -INFINITY;
    #pragma unroll
    for (int k = 0; k < 8; k++) {
        int i = t + k * 512;
        int x = i >> 4, b = i & 15;
        float corr = Acc[x * 17 + b] + Dsh[x * 17 + b];
        float nv = irow[i] + __fdiv_rn(corr, 180.0f);
        irow[i] = nv;
        Dsh[x * 17 + b] = nv;                 // stage for prefix (own slot)
        mx = fmaxf(mx, nv);
    }
    if (last) {
        #pragma unroll
        for (int off = 16; off; off >>= 1)
            mx = fmaxf(mx, __shfl_xor_sync(0xffffffffu, mx, off));
        if (lane == 0) blockmax[w] = mx;
    }
    __syncthreads();
    // Phase E: inclusive prefix of new row -> g_P; same fast scan
    {
        float s[8];
        int base = lane * 8;
        #pragma unroll
        for (int k = 0; k < 8; k++) s[k] = Dsh[(base + k) * 17 + w];
        #pragma unroll
        for (int k = 1; k < 8; k++) s[k] += s[k - 1];
        float tot = s[7], inc = tot;
        #pragma unroll
        for (int off = 1; off < 32; off <<= 1) {
            float nn = __shfl_up_sync(0xffffffffu, inc, off);
            if (lane >= off) inc += nn;
        }
        float excl = inc - tot;
        #pragma unroll
        for (int k = 0; k < 8; k++) Dsh[(base + k) * 17 + w] = s[k] + excl;
    }
    __syncthreads();
    #pragma unroll
    for (int k = 0; k < 8; k++) {
        int i = t + k * 512;
        int x = i >> 4, b = i & 15;
        g_P[((size_t)y * 257 + x + 1) * NB + b] = Dsh[x * 17 + b];
    }
    if (last && t == 0) {
        float m = blockmax[0];
        #pragma unroll
        for (int k = 1; k < 16; k++) m = fmaxf(m, blockmax[k]);
        unsigned u = __float_as_uint(m);
        u = (u & 0x80000000u) ? ~u : (u | 0x80000000u);
        atomicMax(&g_maxbits, u);
    }
}

// fused FP: blocks [0, 5760) interior runs; blocks [5760, 6120) terminal bins
__global__ __launch_bounds__(256) void k_fpx() {
    __shared__ ushort4 sm2[256];
    __shared__ float red[16 * 17];
    int bx = blockIdx.x;
    int t = threadIdx.x;
    if (bx < NRC / 8) {
        // interior FP: warp per (a,d), zero atomics, MLP 8
        int wi = bx * 8 + (t >> 5);
        int d = wi & 255;
        if (d == 0 || d == 255) return;                  // terminal handled below
        int lane = t & 31, half = lane >> 4, b = lane & 15;
        int n = g_cnt[wi];
        const unsigned* runs = g_runs + (size_t)wi * CAP;
        float acc = 0.0f, acc2 = 0.0f, acc3 = 0.0f, acc4 = 0.0f;
        int r = half;
        for (; r + 6 < n; r += 8) {
            unsigned r1 = runs[r], r2 = runs[r + 2], r3 = runs[r + 4], r4 = runs[r + 6];
            const float* P1 = g_P + (size_t)(r1 & 255) * 257 * NB;
            const float* P2 = g_P + (size_t)(r2 & 255) * 257 * NB;
            const float* P3 = g_P + (size_t)(r3 & 255) * 257 * NB;
            const float* P4 = g_P + (size_t)(r4 & 255) * 257 * NB;
            acc  += P1[((r1 >> 17) & 511) * NB + b] - P1[((r1 >> 8) & 511) * NB + b];
            acc2 += P2[((r2 >> 17) & 511) * NB + b] - P2[((r2 >> 8) & 511) * NB + b];
            acc3 += P3[((r3 >> 17) & 511) * NB + b] - P3[((r3 >> 8) & 511) * NB + b];
            acc4 += P4[((r4 >> 17) & 511) * NB + b] - P4[((r4 >> 8) & 511) * NB + b];
        }
        for (; r < n; r += 2) {
            unsigned rec = runs[r];
            const float* Pr = g_P + (size_t)(rec & 255) * 257 * NB;
            acc += Pr[((rec >> 17) & 511) * NB + b] - Pr[((rec >> 8) & 511) * NB + b];
        }
        acc = (acc + acc2) + (acc3 + acc4);
        acc += __shfl_xor_sync(0xffffffffu, acc, 16);
        if (half == 0)
            g_R[(size_t)wi * NB + b] = g_SN[(size_t)wi * NB + b] - acc;
        return;
    }
    // terminal bins d in {0,255}: block per (a,side)
    int bx2 = bx - NRC / 8;
    int a = bx2 >> 1;
    int d = (bx2 & 1) ? 255 : 0;
    sm2[t] = g_meta[a * NH + t];
    __syncthreads();
    int b = t & 15, yg = t >> 4;
    float acc = 0.0f;
    #pragma unroll 4
    for (int i = 0; i < 16; i++) {
        int y = yg * 16 + i;
        ushort4 m = sm2[y];
        const float* Pr = g_P + (size_t)y * 257 * NB;
        if ((int)m.z == d)        acc += Pr[(int)m.x * NB + b];
        else if ((int)m.w == d)   acc += Pr[256 * NB + b] - Pr[(int)m.y * NB + b];
    }
    red[yg * 17 + b] = acc;
    __syncthreads();
    if (t < 16) {
        float s = 0.0f;
        #pragma unroll
        for (int g = 0; g < 16; g++) s += red[g * 17 + t];
        int wi = a * ND + d;
        g_R[(size_t)wi * NB + t] = g_SN[(size_t)wi * NB + t] - s;
    }
}

// output: clip(image, 0, gmax), coalesced transpose [p][b] -> [b][p]
__global__ __launch_bounds__(256) void k_out(float* __restrict__ out) {
    __shared__ float sh[256 * 17];
    int t = threadIdx.x;
    int p0 = blockIdx.x * 256;
    const float* src = g_img + (size_t)p0 * NB;
    for (int i = t; i < 256 * NB; i += 256) {
        int p = i >> 4, b = i & 15;
        sh[p * 17 + b] = src[i];
    }
    __syncthreads();
    unsigned u = g_maxbits;
    float gm = (u & 0x80000000u) ? __uint_as_float(u ^ 0x80000000u)
                                 : __uint_as_float(~u);
    #pragma unroll
    for (int b = 0; b < NB; b++) {
        float v = sh[t * 17 + b];
        out[(size_t)b * NP + p0 + t] = fminf(fmaxf(v, 0.0f), gm);
    }
}

extern "C" void kernel_launch(void* const* d_in, const int* in_sizes, int n_in,
                              void* d_out, int out_size) {
    const float* sino = (const float*)d_in[0];
    float* out = (float*)d_out;

    k_pre<<<64, 256>>>();
    k_pre2<<<512, 256>>>(sino);
    k_binsfill<<<dim3(NA, 8), 256>>>();
    // NOTE: iteration 0's BP runs before the loop; first k_fpx is launch #4+1?
    // Order: pre(1), pre2(2), binsfill(3), fpx? -> put bp(it0) after first fpx
    // is NOT valid (fpx needs P from bp). Keep bp(it0) at #4? Already profiled.
    // Instead profile fpx: bp(it0) must precede it; accept slot #5? The
    // profiler takes #4 = bp(it0) again; we already have its new numbers ->
    // fine, confirms the Phase B fix directly against 36.5us.
    k_bp<<<NH, 512>>>(0);                // launch #4 -> ncu target (A/B test)
    for (int it = 1; it < NT; it++) {
        k_fpx<<<NRC / 8 + NA * 2, 256>>>();
        k_bp<<<NH, 512>>>(it == NT - 1 ? 1 : 0);
    }
    k_out<<<256, 256>>>(out);
}